// round 15
// baseline (speedup 1.0000x reference)
#include <cuda_runtime.h>
#include <cuda_fp16.h>
#include <cstdint>

// Problem constants (match reference)
#define T_STEPS 100
#define BATCH   32
#define NIN     1024
#define NOUT    512
#define K_TOT   3200

#define LR_LTP  1e-4f
#define DECAY      0.951229424500714f    // exp(-1/20)
#define INV_DECAY  1.0512710963760241f   // exp(+1/20)
#define D24        0.3011942119122021f   // exp(-24/20)
#define D25        0.2865047968601901f   // exp(-25/20)
#define D49        0.0862935864993704f   // exp(-49/20)
#define D50        0.0820849986238988f   // exp(-50/20)
#define D74        0.0247235264703394f   // exp(-74/20)
#define D75        0.0235177458560091f   // exp(-75/20)

// Device scratch (allocation-free). All [k, col] natural layouts.
__device__ __align__(16) __half g_pre_tr_h [K_TOT * NIN];   // [k, i] traces
__device__ __align__(16) __half g_post_tr_h[K_TOT * NOUT];  // [k, o]
__device__ __align__(16) __half g_pre_s16  [K_TOT * NIN];   // [k, i] fp16 spikes
__device__ __align__(16) __half g_post_s16 [K_TOT * NOUT];  // [k, o]
__device__ __align__(16) float  g_part[8][NOUT * NIN];      // [gemm*4+split]

// ============================ 1) Traces ====================================
// T chunked in 4. Thread = (chunk c, b, col). Carry for chunk c is a dot
// product over the preceding 25c spikes (parallel loads), then 25 serial
// steps writing fp16 trace + fp16 spike history. Spike re-reads are
// L2-resident -> default-cached loads (NOT __ldcs).
#define NCH   4
#define TC    25
#define PRE_CTAS  ((NCH * BATCH * NIN ) / 256)   // 512
#define POST_CTAS ((NCH * BATCH * NOUT) / 256)   // 256
#define UB 5

__device__ __forceinline__ void trace_chunk(const float* __restrict__ spikes,
                                            const float* __restrict__ trace0,
                                            __half* __restrict__ tr_h,
                                            __half* __restrict__ s16,
                                            float* __restrict__ out_tr,
                                            int stride, int c, int idx)
{
    float tr;
    if (c == 0) {
        tr = trace0[idx];
    } else {
        // carry = D^(25c)*tr0 + sum_{t<25c} D^(25c-1-t) * s[t]
        const float w0 = (c == 1) ? D24 : (c == 2) ? D49 : D74;
        const float dc = (c == 1) ? D25 : (c == 2) ? D50 : D75;
        float acc0 = 0.f, acc1 = 0.f, w = w0;
        const int tc = c * TC;
        for (int t0 = 0; t0 < tc; t0 += UB) {
            float s[UB];
            #pragma unroll
            for (int u = 0; u < UB; ++u)
                s[u] = spikes[(t0 + u) * stride + idx];
            #pragma unroll
            for (int u = 0; u < UB; ++u) {
                if (u & 1) acc1 = fmaf(w, s[u], acc1);
                else       acc0 = fmaf(w, s[u], acc0);
                w *= INV_DECAY;
            }
        }
        tr = fmaf(dc, trace0[idx], acc0 + acc1);
    }
    const int tb = c * TC;
    for (int t0 = tb; t0 < tb + TC; t0 += UB) {
        float s[UB];
        #pragma unroll
        for (int u = 0; u < UB; ++u)
            s[u] = spikes[(t0 + u) * stride + idx];
        #pragma unroll
        for (int u = 0; u < UB; ++u) {
            const int a = (t0 + u) * stride + idx;
            tr = tr * DECAY + s[u];
            tr_h[a] = __float2half_rn(tr);
            s16[a]  = __float2half_rn(s[u]);
        }
    }
    if (c == NCH - 1) out_tr[idx] = tr;
}

__global__ void __launch_bounds__(256)
traces_fused_kernel(const float* __restrict__ pre_spikes,
                    const float* __restrict__ post_spikes,
                    const float* __restrict__ pre_trace0,
                    const float* __restrict__ post_trace0,
                    float* __restrict__ out_pre_tr,
                    float* __restrict__ out_post_tr)
{
    if (blockIdx.x < PRE_CTAS) {
        const int g   = blockIdx.x * 256 + threadIdx.x;
        const int c   = g >> 15;                 // chunk 0..3
        const int idx = g & 32767;               // b*NIN + i
        trace_chunk(pre_spikes, pre_trace0, g_pre_tr_h, g_pre_s16,
                    out_pre_tr, BATCH * NIN, c, idx);
    } else {
        const int g   = (blockIdx.x - PRE_CTAS) * 256 + threadIdx.x;
        const int c   = g >> 14;
        const int idx = g & 16383;               // b*NOUT + o
        trace_chunk(post_spikes, post_trace0, g_post_tr_h, g_post_s16,
                    out_post_tr, BATCH * NOUT, c, idx);
    }
}

// ============================ 2) GEMM (mma.sync) ===========================
// UNCHANGED from R14 (verified: 2.98e-5, ~17us).
// D[m,n] = sum_k A[k,m] * B[k,n];  A = post [k,NOUT], B = pre [k,NIN].
// GEMM0 (LTP): A=post_s16, B=pre_tr.  GEMM1 (LTD): A=post_tr, B=pre_s16.
// 256 CTAs: gemm(1b) | split(2b,=4) | mt(2b) | nt(3b). CTA tile 128x128,
// BK=32, 3-stage cp.async pipeline, 8 warps (2x4), warp tile 64x32.
#define KSPLIT   800
#define BK       32
#define NCHUNKS  (KSPLIT / BK)    // 25
#define LDT      136              // halves per smem row (272B: %16B==0, 8-row
                                  // ldmatrix addrs cover all 32 banks)
#define TILE_B2  (BK * LDT * 2)   // 8704 bytes per operand tile
#define STAGE_B  (2 * TILE_B2)    // 17408 bytes (A + B)
#define NSTAGE   3
#define GEMM_SMEM (NSTAGE * STAGE_B)   // 52224

__device__ __forceinline__ uint32_t smem_u32(const void* p) {
    uint32_t a;
    asm("{ .reg .u64 t; cvta.to.shared.u64 t, %1; cvt.u32.u64 %0, t; }"
        : "=r"(a) : "l"(p));
    return a;
}
#define CP_ASYNC16(dst, src) \
    asm volatile("cp.async.cg.shared.global [%0], [%1], 16;" :: "r"(dst), "l"(src))
#define CP_COMMIT() asm volatile("cp.async.commit_group;" ::: "memory")
#define CP_WAIT2()  asm volatile("cp.async.wait_group 2;" ::: "memory")

#define LDMATRIX_X4_T(r0, r1, r2, r3, addr) \
    asm volatile("ldmatrix.sync.aligned.m8n8.x4.trans.shared.b16 {%0,%1,%2,%3}, [%4];" \
        : "=r"(r0), "=r"(r1), "=r"(r2), "=r"(r3) : "r"(addr))

#define MMA16816(d0, d1, d2, d3, a0, a1, a2, a3, b0, b1) \
    asm volatile("mma.sync.aligned.m16n8k16.row.col.f32.f16.f16.f32 " \
        "{%0,%1,%2,%3}, {%4,%5,%6,%7}, {%8,%9}, {%0,%1,%2,%3};" \
        : "+f"(d0), "+f"(d1), "+f"(d2), "+f"(d3) \
        : "r"(a0), "r"(a1), "r"(a2), "r"(a3), "r"(b0), "r"(b1))

__global__ void __launch_bounds__(256, 2)
stdp_gemm_kernel()
{
    extern __shared__ __align__(16) char smem[];
    const uint32_t sbase = smem_u32(smem);

    const int tid  = threadIdx.x;
    const int wid  = tid >> 5;
    const int lane = tid & 31;
    const int bid  = blockIdx.x;
    const int gm   = bid >> 7;
    const int sp   = (bid >> 5) & 3;
    const int mt   = (bid >> 3) & 3;
    const int nt   = bid & 7;

    const __half* Ap = gm ? g_post_tr_h : g_post_s16;   // [k, NOUT]
    const __half* Bp = gm ? g_pre_s16   : g_pre_tr_h;   // [k, NIN]
    const int m0 = mt * 128, n0 = nt * 128, kb = sp * KSPLIT;

    const int lrow = tid >> 3;
    const int lc0  = (tid & 7) * 8;    // halves

    auto issue_chunk = [&](int c, int stage) {
        const int krow = kb + c * BK + lrow;
        const uint32_t dA = sbase + stage * STAGE_B + lrow * (LDT * 2) + lc0 * 2;
        const uint32_t dB = dA + TILE_B2;
        const __half* sa = Ap + (size_t)krow * NOUT + m0 + lc0;
        const __half* sb = Bp + (size_t)krow * NIN  + n0 + lc0;
        CP_ASYNC16(dA,           sa);
        CP_ASYNC16(dA + 128,     sa + 64);
        CP_ASYNC16(dB,           sb);
        CP_ASYNC16(dB + 128,     sb + 64);
    };

    const int wm = (wid & 1) * 64;
    const int wn = (wid >> 1) * 32;
    const int r  = lane & 7;
    const int j  = lane >> 3;

    float acc[4][4][4];
    #pragma unroll
    for (int mi = 0; mi < 4; ++mi)
        #pragma unroll
        for (int ni = 0; ni < 4; ++ni)
            #pragma unroll
            for (int q = 0; q < 4; ++q) acc[mi][ni][q] = 0.f;

    issue_chunk(0, 0); CP_COMMIT();
    issue_chunk(1, 1); CP_COMMIT();
    issue_chunk(2, 2); CP_COMMIT();

    for (int c = 0; c < NCHUNKS; ++c) {
        CP_WAIT2();
        __syncthreads();
        const uint32_t tA = sbase + (c % NSTAGE) * STAGE_B;
        const uint32_t tB = tA + TILE_B2;

        #pragma unroll
        for (int kk = 0; kk < BK / 16; ++kk) {
            const int k0 = kk * 16;
            uint32_t a[4][4];
            #pragma unroll
            for (int mi = 0; mi < 4; ++mi) {
                const int mf = wm + mi * 16;
                const uint32_t ad = tA + (uint32_t)(k0 + (j >> 1) * 8 + r) * (LDT * 2)
                                       + (uint32_t)(mf + (j & 1) * 8) * 2;
                LDMATRIX_X4_T(a[mi][0], a[mi][1], a[mi][2], a[mi][3], ad);
            }
            uint32_t b[4][2];
            #pragma unroll
            for (int nj = 0; nj < 2; ++nj) {
                const int nf = wn + nj * 16;
                const uint32_t bd = tB + (uint32_t)(k0 + (j & 1) * 8 + r) * (LDT * 2)
                                       + (uint32_t)(nf + (j >> 1) * 8) * 2;
                uint32_t r0, r1, r2, r3;
                LDMATRIX_X4_T(r0, r1, r2, r3, bd);
                b[nj * 2 + 0][0] = r0; b[nj * 2 + 0][1] = r1;
                b[nj * 2 + 1][0] = r2; b[nj * 2 + 1][1] = r3;
            }
            #pragma unroll
            for (int mi = 0; mi < 4; ++mi)
                #pragma unroll
                for (int ni = 0; ni < 4; ++ni)
                    MMA16816(acc[mi][ni][0], acc[mi][ni][1], acc[mi][ni][2], acc[mi][ni][3],
                             a[mi][0], a[mi][1], a[mi][2], a[mi][3],
                             b[ni][0], b[ni][1]);
        }
        __syncthreads();
        if (c + 3 < NCHUNKS) issue_chunk(c + 3, c % NSTAGE);
        CP_COMMIT();
    }

    const int dg = lane >> 2;
    const int dc = (lane & 3) * 2;
    float* dst = &g_part[gm * 4 + sp][0];
    #pragma unroll
    for (int mi = 0; mi < 4; ++mi)
        #pragma unroll
        for (int ni = 0; ni < 4; ++ni) {
            const int row = m0 + wm + mi * 16 + dg;
            const int col = n0 + wn + ni * 8 + dc;
            *(float2*)&dst[(size_t)row * NIN + col] =
                make_float2(acc[mi][ni][0], acc[mi][ni][1]);
            *(float2*)&dst[(size_t)(row + 8) * NIN + col] =
                make_float2(acc[mi][ni][2], acc[mi][ni][3]);
        }
}

// ============================ 3) Combine ===================================
__global__ void __launch_bounds__(256)
combine_kernel(const float* __restrict__ weight,
               float* __restrict__ delta_w)
{
    const float s = LR_LTP / (float)BATCH;
    const int idx = (blockIdx.x * 256 + threadIdx.x) * 4;
    float4 w = *(const float4*)(weight + idx);
    float4 p = *(const float4*)(&g_part[0][idx]);
    float4 d = *(const float4*)(&g_part[4][idx]);
    #pragma unroll
    for (int q = 1; q < 4; ++q) {
        float4 pq = *(const float4*)(&g_part[q][idx]);
        float4 dq = *(const float4*)(&g_part[4 + q][idx]);
        p.x += pq.x; p.y += pq.y; p.z += pq.z; p.w += pq.w;
        d.x += dq.x; d.y += dq.y; d.z += dq.z; d.w += dq.w;
    }
    float4 r;
    r.x = s * ((1.f - w.x) * p.x - w.x * d.x);
    r.y = s * ((1.f - w.y) * p.y - w.y * d.y);
    r.z = s * ((1.f - w.z) * p.z - w.z * d.z);
    r.w = s * ((1.f - w.w) * p.w - w.w * d.w);
    *(float4*)(delta_w + idx) = r;
}

// ===========================================================================
extern "C" void kernel_launch(void* const* d_in, const int* in_sizes, int n_in,
                              void* d_out, int out_size)
{
    const float* weight      = (const float*)d_in[0];  // [NOUT, NIN]
    const float* pre_spikes  = (const float*)d_in[1];  // [T, B, NIN]
    const float* post_spikes = (const float*)d_in[2];  // [T, B, NOUT]
    const float* pre_trace0  = (const float*)d_in[3];  // [B, NIN]
    const float* post_trace0 = (const float*)d_in[4];  // [B, NOUT]

    float* out         = (float*)d_out;
    float* out_delta_w = out;                              // 512*1024
    float* out_pre_tr  = out + NOUT * NIN;                 // 32*1024
    float* out_post_tr = out + NOUT * NIN + BATCH * NIN;   // 32*512

    cudaFuncSetAttribute(stdp_gemm_kernel,
                         cudaFuncAttributeMaxDynamicSharedMemorySize, GEMM_SMEM);

    // 1) Traces + fp16 spike conversion, T chunked in 4 (196K threads)
    traces_fused_kernel<<<PRE_CTAS + POST_CTAS, 256>>>(
        pre_spikes, post_spikes, pre_trace0, post_trace0,
        out_pre_tr, out_post_tr);

    // 2) Dual f16 GEMM via mma.sync + ldmatrix + cp.async, split-K=4
    stdp_gemm_kernel<<<256, 256, GEMM_SMEM>>>();

    // 3) Combine 8 partials + soft-bound epilogue
    combine_kernel<<<(NOUT * NIN / 4) / 256, 256>>>(weight, out_delta_w);
}